// round 1
// baseline (speedup 1.0000x reference)
#include <cuda_runtime.h>
#include <cuda_bf16.h>
#include <cstdint>

// Problem constants (Wisard_68401649156855)
#define ENTRY_SIZE 1024
#define N_CLASSES  10
#define TUPLE_SIZE 16
#define N_RAMS     64          // ENTRY_SIZE / TUPLE_SIZE
#define N_ADDR     65536       // 1 << TUPLE_SIZE
#define BATCH      8192
#define WORDS_PER_ROW 32       // 1024 bits / 32

// Scratch: transposed packed sample bits, bitsT[w][b] (w = word index 0..31, b = sample)
__device__ unsigned g_bitsT[WORDS_PER_ROW * BATCH];

// ---------------------------------------------------------------------------
// Kernel 1: pack samples (int32 0/1) into transposed bit matrix via ballot.
// warpId = w*BATCH + b  ->  w = warpId >> 13, b = warpId & 8191
// Each warp: 32 coalesced int loads + 1 ballot + 1 store.
// Consecutive warps in a block share w and have consecutive b -> coalesced stores.
// ---------------------------------------------------------------------------
__global__ void __launch_bounds__(256) wisard_pack_kernel(const int* __restrict__ samples)
{
    int gtid   = blockIdx.x * blockDim.x + threadIdx.x;
    int warpId = gtid >> 5;
    int lane   = gtid & 31;
    int w = warpId >> 13;          // 0..31
    int b = warpId & (BATCH - 1);  // 0..8191

    int v = samples[b * ENTRY_SIZE + w * 32 + lane];
    unsigned m = __ballot_sync(0xffffffffu, v != 0);
    if (lane == 0) g_bitsT[w * BATCH + b] = m;
}

// ---------------------------------------------------------------------------
// Kernel 2: main WiSARD lookup.
// Grid: (BATCH/256, N_CLASSES). Block: 256 threads, one sample per thread.
// Sample bit-row lives in padded shared memory (stride 33 -> conflict-free
// dynamic LDS). tuple_mapping for the class cached in shared, read as int4.
// ---------------------------------------------------------------------------
__global__ void __launch_bounds__(256) wisard_main_kernel(
    const int*   __restrict__ tuple_mapping,  // [N_CLASSES][ENTRY_SIZE]
    const float* __restrict__ ram_table,      // [N_CLASSES][N_RAMS][N_ADDR]
    float*       __restrict__ out)            // [BATCH][N_CLASSES]
{
    const int c    = blockIdx.y;
    const int tid  = threadIdx.x;
    const int b    = blockIdx.x * 256 + tid;

    __shared__ __align__(16) int tm_s[ENTRY_SIZE];
    __shared__ unsigned rows[256 * 33];        // +1 word pad per row -> no bank conflicts

    // Load this class's tuple mapping (4 KB, coalesced)
    #pragma unroll
    for (int i = 0; i < ENTRY_SIZE / 256; ++i)
        tm_s[tid + i * 256] = tuple_mapping[c * ENTRY_SIZE + tid + i * 256];

    // Load this thread's packed sample row (coalesced across threads per word)
    unsigned* row = rows + tid * 33;
    #pragma unroll
    for (int w = 0; w < WORDS_PER_ROW; ++w)
        row[w] = g_bitsT[w * BATCH + b];

    __syncthreads();

    const float* tbl = ram_table + (size_t)c * (N_RAMS * N_ADDR);
    const int4* tmv = (const int4*)tm_s;

    float acc0 = 0.f, acc1 = 0.f;

    #pragma unroll 4
    for (int r = 0; r < N_RAMS; ++r) {
        unsigned addr = 0u;
        #pragma unroll
        for (int q = 0; q < 4; ++q) {
            int4 p = tmv[r * 4 + q];
            // first tuple element is the MSB: addr = (addr<<1) | bit, 16 times
            addr = (addr << 1) | ((row[p.x >> 5] >> (p.x & 31)) & 1u);
            addr = (addr << 1) | ((row[p.y >> 5] >> (p.y & 31)) & 1u);
            addr = (addr << 1) | ((row[p.z >> 5] >> (p.z & 31)) & 1u);
            addr = (addr << 1) | ((row[p.w >> 5] >> (p.w & 31)) & 1u);
        }
        float v = __ldg(tbl + (r << TUPLE_SIZE) + addr);
        if (r & 1) acc1 += v; else acc0 += v;
    }

    out[b * N_CLASSES + c] = acc0 + acc1;
}

// ---------------------------------------------------------------------------
// Launch
// ---------------------------------------------------------------------------
extern "C" void kernel_launch(void* const* d_in, const int* in_sizes, int n_in,
                              void* d_out, int out_size)
{
    const int*   samples       = (const int*)  d_in[0];  // [8192][1024] int32
    const int*   tuple_mapping = (const int*)  d_in[1];  // [10][1024]   int32
    const float* ram_table     = (const float*)d_in[2];  // [10][64][65536] float32
    float*       out           = (float*)d_out;          // [8192][10]   float32

    // Pack: 32*8192 warps = 262144 warps -> 8.39M threads / 256 = 32768 blocks
    wisard_pack_kernel<<<(WORDS_PER_ROW * BATCH * 32) / 256, 256>>>(samples);

    dim3 grid(BATCH / 256, N_CLASSES);
    wisard_main_kernel<<<grid, 256>>>(tuple_mapping, ram_table, out);
}

// round 4
// speedup vs baseline: 1.8778x; 1.8778x over previous
#include <cuda_runtime.h>
#include <cuda_bf16.h>
#include <cstdint>

// Problem constants (Wisard_68401649156855)
#define ENTRY_SIZE 1024
#define N_CLASSES  10
#define TUPLE_SIZE 16
#define N_RAMS     64          // ENTRY_SIZE / TUPLE_SIZE
#define N_ADDR     65536       // 1 << TUPLE_SIZE
#define BATCH      8192
#define WORDS_PER_ROW 32       // 1024 bits / 32

#define S_PER_BLOCK 64         // samples per block
#define R_GROUPS    4          // r-split per sample (16 RAMs each)

// Scratch: transposed packed sample bits, bitsT[w][b] (w = word index, b = sample)
__device__ unsigned g_bitsT[WORDS_PER_ROW * BATCH];

// ---------------------------------------------------------------------------
// Kernel 1: pack samples (int32 0/1) into transposed bit matrix via ballot.
// Each warp handles 4 consecutive words (128 elements) of one sample row.
// 4 loads issued up-front (MLP=4), then 4 ballots + stores.
// ---------------------------------------------------------------------------
__global__ void __launch_bounds__(256) wisard_pack_kernel(const int* __restrict__ samples)
{
    int gtid   = blockIdx.x * blockDim.x + threadIdx.x;
    int warpId = gtid >> 5;
    int lane   = gtid & 31;
    int b      = warpId >> 3;           // 8 warps per sample row
    int wbase  = (warpId & 7) * 4;      // first of 4 words this warp produces

    const int* base = samples + (size_t)b * ENTRY_SIZE + wbase * 32 + lane;
    int v0 = base[0];
    int v1 = base[32];
    int v2 = base[64];
    int v3 = base[96];

    unsigned m0 = __ballot_sync(0xffffffffu, v0 != 0);
    unsigned m1 = __ballot_sync(0xffffffffu, v1 != 0);
    unsigned m2 = __ballot_sync(0xffffffffu, v2 != 0);
    unsigned m3 = __ballot_sync(0xffffffffu, v3 != 0);

    if (lane == 0) {
        g_bitsT[(wbase + 0) * BATCH + b] = m0;
        g_bitsT[(wbase + 1) * BATCH + b] = m1;
        g_bitsT[(wbase + 2) * BATCH + b] = m2;
        g_bitsT[(wbase + 3) * BATCH + b] = m3;
    }
}

// ---------------------------------------------------------------------------
// Kernel 2: main WiSARD lookup, r-split for occupancy.
// Grid: (BATCH/64, N_CLASSES). Block: 256 threads.
// Thread (s = tid>>2, g = tid&3) handles sample s, RAMs [g*16, g*16+16).
// The 4 partial sums for a sample live in adjacent lanes -> shfl_xor reduce.
// ---------------------------------------------------------------------------
__global__ void __launch_bounds__(256) wisard_main_kernel(
    const int*   __restrict__ tuple_mapping,  // [N_CLASSES][ENTRY_SIZE]
    const float* __restrict__ ram_table,      // [N_CLASSES][N_RAMS][N_ADDR]
    float*       __restrict__ out)            // [BATCH][N_CLASSES]
{
    const int c     = blockIdx.y;
    const int tid   = threadIdx.x;
    const int s     = tid >> 2;          // sample within block (0..63)
    const int g     = tid & 3;           // r-group (0..3)
    const int bbase = blockIdx.x * S_PER_BLOCK;
    const int b     = bbase + s;

    __shared__ __align__(16) int tm_s[ENTRY_SIZE];
    __shared__ unsigned rows[S_PER_BLOCK * 33];   // +1 word pad -> fewer bank conflicts

    // Load this class's tuple mapping (4 KB, coalesced)
    #pragma unroll
    for (int i = 0; i < ENTRY_SIZE / 256; ++i)
        tm_s[tid + i * 256] = tuple_mapping[c * ENTRY_SIZE + tid + i * 256];

    // Load the 64 packed sample rows (64 samples x 32 words, coalesced:
    // consecutive tid -> consecutive samples within one word column)
    #pragma unroll
    for (int i = 0; i < (S_PER_BLOCK * WORDS_PER_ROW) / 256; ++i) {
        int idx = i * 256 + tid;
        int w   = idx >> 6;            // 0..31
        int s2  = idx & 63;            // 0..63
        rows[s2 * 33 + w] = g_bitsT[w * BATCH + bbase + s2];
    }

    __syncthreads();

    const unsigned* row = rows + s * 33;
    const float* tbl = ram_table + (size_t)c * (N_RAMS * N_ADDR);
    const int4* tmv = (const int4*)tm_s;

    float acc = 0.f;

    #pragma unroll 4
    for (int i = 0; i < 16; ++i) {
        const int r = g * 16 + i;
        unsigned addr = 0u;
        #pragma unroll
        for (int q = 0; q < 4; ++q) {
            int4 p = tmv[r * 4 + q];
            // first tuple element is the MSB
            addr = (addr << 1) | ((row[p.x >> 5] >> (p.x & 31)) & 1u);
            addr = (addr << 1) | ((row[p.y >> 5] >> (p.y & 31)) & 1u);
            addr = (addr << 1) | ((row[p.z >> 5] >> (p.z & 31)) & 1u);
            addr = (addr << 1) | ((row[p.w >> 5] >> (p.w & 31)) & 1u);
        }
        acc += __ldg(tbl + ((size_t)r << TUPLE_SIZE) + addr);
    }

    // Reduce the 4 r-group partials (adjacent lanes)
    acc += __shfl_xor_sync(0xffffffffu, acc, 1);
    acc += __shfl_xor_sync(0xffffffffu, acc, 2);

    if (g == 0)
        out[b * N_CLASSES + c] = acc;
}

// ---------------------------------------------------------------------------
// Launch
// ---------------------------------------------------------------------------
extern "C" void kernel_launch(void* const* d_in, const int* in_sizes, int n_in,
                              void* d_out, int out_size)
{
    const int*   samples       = (const int*)  d_in[0];  // [8192][1024] int32
    const int*   tuple_mapping = (const int*)  d_in[1];  // [10][1024]   int32
    const float* ram_table     = (const float*)d_in[2];  // [10][64][65536] float32
    float*       out           = (float*)d_out;          // [8192][10]   float32

    // Pack: 8 warps per sample row -> 8192*8 warps -> 2,097,152 threads
    wisard_pack_kernel<<<(BATCH * 8 * 32) / 256, 256>>>(samples);

    dim3 grid(BATCH / S_PER_BLOCK, N_CLASSES);
    wisard_main_kernel<<<grid, 256>>>(tuple_mapping, ram_table, out);
}

// round 7
// speedup vs baseline: 2.7985x; 1.4903x over previous
#include <cuda_runtime.h>
#include <cuda_bf16.h>
#include <cstdint>

// Problem constants (Wisard_68401649156855)
#define ENTRY_SIZE 1024
#define N_CLASSES  10
#define TUPLE_SIZE 16
#define N_RAMS     64          // ENTRY_SIZE / TUPLE_SIZE
#define N_ADDR     65536       // 1 << TUPLE_SIZE
#define BATCH      8192
#define WORDS_PER_ROW 32       // 1024 bits / 32

// Scratch: transposed packed sample bits, bitsT[w][b]
// bit k of bitsT[w][b] = samples[b][w*32+k]
__device__ unsigned g_bitsT[WORDS_PER_ROW * BATCH];

// ---------------------------------------------------------------------------
// Kernel 1: pack samples (int32 0/1) into bit matrix via ballot. MLP=8.
// Each warp produces 8 consecutive words (256 entries) of one sample row.
// ---------------------------------------------------------------------------
__global__ void __launch_bounds__(256) wisard_pack_kernel(const int* __restrict__ samples)
{
    int gtid   = blockIdx.x * blockDim.x + threadIdx.x;
    int warpId = gtid >> 5;
    int lane   = gtid & 31;
    int b      = warpId >> 2;           // 4 warps per sample row
    int wbase  = (warpId & 3) * 8;      // first of 8 words this warp produces

    const int* base = samples + (size_t)b * ENTRY_SIZE + wbase * 32 + lane;
    int v0 = base[0];
    int v1 = base[32];
    int v2 = base[64];
    int v3 = base[96];
    int v4 = base[128];
    int v5 = base[160];
    int v6 = base[192];
    int v7 = base[224];

    unsigned m0 = __ballot_sync(0xffffffffu, v0 != 0);
    unsigned m1 = __ballot_sync(0xffffffffu, v1 != 0);
    unsigned m2 = __ballot_sync(0xffffffffu, v2 != 0);
    unsigned m3 = __ballot_sync(0xffffffffu, v3 != 0);
    unsigned m4 = __ballot_sync(0xffffffffu, v4 != 0);
    unsigned m5 = __ballot_sync(0xffffffffu, v5 != 0);
    unsigned m6 = __ballot_sync(0xffffffffu, v6 != 0);
    unsigned m7 = __ballot_sync(0xffffffffu, v7 != 0);

    if (lane == 0) {
        g_bitsT[(wbase + 0) * BATCH + b] = m0;
        g_bitsT[(wbase + 1) * BATCH + b] = m1;
        g_bitsT[(wbase + 2) * BATCH + b] = m2;
        g_bitsT[(wbase + 3) * BATCH + b] = m3;
        g_bitsT[(wbase + 4) * BATCH + b] = m4;
        g_bitsT[(wbase + 5) * BATCH + b] = m5;
        g_bitsT[(wbase + 6) * BATCH + b] = m6;
        g_bitsT[(wbase + 7) * BATCH + b] = m7;
    }
}

// ---------------------------------------------------------------------------
// 32x32 bit-matrix transpose across a warp (block-swap butterfly).
// Input: lane l holds word x, bit k = M[l][k].
// Output: lane j holds word with bit k = M[k][j].
// ---------------------------------------------------------------------------
__device__ __forceinline__ unsigned warp_bit_transpose(unsigned x, int lane)
{
    const unsigned masks[5] = { 0x0000FFFFu, 0x00FF00FFu, 0x0F0F0F0Fu,
                                0x33333333u, 0x55555555u };
    const int shifts[5] = { 16, 8, 4, 2, 1 };
    #pragma unroll
    for (int i = 0; i < 5; ++i) {
        int s = shifts[i];
        unsigned lm = masks[i];
        unsigned y = __shfl_xor_sync(0xffffffffu, x, s);
        if ((lane & s) == 0)
            x = (x & lm) | ((y & lm) << s);
        else
            x = (x & ~lm) | ((y & ~lm) >> s);
    }
    return x;
}

// ---------------------------------------------------------------------------
// Kernel 2: main WiSARD lookup with entry-major bit words.
// Grid: (BATCH/32, N_CLASSES). Block: 256 threads = 8 warps.
// Block handles 32 samples (group bw) for class c.
// Phase 1: transpose bitsT tiles -> bitS_s[e] (word over the 32 samples).
// Phase 2: warp wid handles RAMs [wid*8, wid*8+8). For each RAM, the 16
//          tuple-entry words are UNIFORM broadcast LDS; each lane extracts
//          bit `lane` -> 32 addresses built per 16 broadcast loads.
// Phase 3: cross-warp reduction, warp 0 writes 32 outputs.
// ---------------------------------------------------------------------------
__global__ void __launch_bounds__(256) wisard_main_kernel(
    const int*   __restrict__ tuple_mapping,  // [N_CLASSES][ENTRY_SIZE]
    const float* __restrict__ ram_table,      // [N_CLASSES][N_RAMS][N_ADDR]
    float*       __restrict__ out)            // [BATCH][N_CLASSES]
{
    const int c    = blockIdx.y;
    const int bw   = blockIdx.x;          // sample group (32 samples)
    const int tid  = threadIdx.x;
    const int wid  = tid >> 5;            // 0..7
    const int lane = tid & 31;

    __shared__ __align__(16) int      tm_s[ENTRY_SIZE];     // 4 KB
    __shared__ unsigned               bitS_s[ENTRY_SIZE];   // 4 KB, word per entry
    __shared__ float                  red[8][32];           // 1 KB

    // Load this class's tuple mapping (coalesced)
    #pragma unroll
    for (int i = 0; i < ENTRY_SIZE / 256; ++i)
        tm_s[tid + i * 256] = tuple_mapping[c * ENTRY_SIZE + tid + i * 256];

    // Phase 1: each warp transposes 4 of the 32 bitsT tiles for this group.
    #pragma unroll
    for (int k = 0; k < 4; ++k) {
        int w = wid * 4 + k;
        unsigned x = g_bitsT[w * BATCH + bw * 32 + lane];   // coalesced
        x = warp_bit_transpose(x, lane);
        // lane j now holds the word for entry w*32+j over the 32 samples
        bitS_s[w * 32 + lane] = x;                          // conflict-free
    }

    __syncthreads();

    const float* tbl = ram_table + (size_t)c * (N_RAMS * N_ADDR);
    const int4* tmv = (const int4*)tm_s;

    float acc0 = 0.f, acc1 = 0.f;

    // Phase 2: 8 RAMs per warp, fully unrolled for load-ahead / MLP.
    #pragma unroll
    for (int i = 0; i < 8; ++i) {
        const int r = wid * 8 + i;
        unsigned addr = 0u;
        #pragma unroll
        for (int q = 0; q < 4; ++q) {
            int4 p = tmv[r * 4 + q];     // uniform per warp
            addr = (addr << 1) | ((bitS_s[p.x] >> lane) & 1u);
            addr = (addr << 1) | ((bitS_s[p.y] >> lane) & 1u);
            addr = (addr << 1) | ((bitS_s[p.z] >> lane) & 1u);
            addr = (addr << 1) | ((bitS_s[p.w] >> lane) & 1u);
        }
        float v = __ldg(tbl + ((size_t)r << TUPLE_SIZE) + addr);
        if (i & 1) acc1 += v; else acc0 += v;
    }

    // Phase 3: reduce the 8 warp partials per sample.
    red[wid][lane] = acc0 + acc1;
    __syncthreads();

    if (wid == 0) {
        float s = red[0][lane];
        #pragma unroll
        for (int w = 1; w < 8; ++w) s += red[w][lane];
        out[(bw * 32 + lane) * N_CLASSES + c] = s;
    }
}

// ---------------------------------------------------------------------------
// Launch
// ---------------------------------------------------------------------------
extern "C" void kernel_launch(void* const* d_in, const int* in_sizes, int n_in,
                              void* d_out, int out_size)
{
    const int*   samples       = (const int*)  d_in[0];  // [8192][1024] int32
    const int*   tuple_mapping = (const int*)  d_in[1];  // [10][1024]   int32
    const float* ram_table     = (const float*)d_in[2];  // [10][64][65536] float32
    float*       out           = (float*)d_out;          // [8192][10]   float32

    // Pack: 4 warps per sample row -> 8192*4*32 threads -> 4096 blocks
    wisard_pack_kernel<<<(BATCH * 4 * 32) / 256, 256>>>(samples);

    dim3 grid(BATCH / 32, N_CLASSES);   // 256 x 10 = 2560 blocks
    wisard_main_kernel<<<grid, 256>>>(tuple_mapping, ram_table, out);
}

// round 8
// speedup vs baseline: 3.1252x; 1.1167x over previous
#include <cuda_runtime.h>
#include <cuda_bf16.h>
#include <cstdint>

// Problem constants (Wisard_68401649156855)
#define ENTRY_SIZE 1024
#define N_CLASSES  10
#define TUPLE_SIZE 16
#define N_RAMS     64
#define N_ADDR     65536
#define BATCH      8192
#define WORDS_PER_ROW 32

// Scratch: transposed packed sample bits, bitsT[w][b]
// bit k of bitsT[w][b] = samples[b][w*32+k]
__device__ unsigned g_bitsT[WORDS_PER_ROW * BATCH];

// ---------------------------------------------------------------------------
// Kernel 1: pack samples (int32 0/1) -> bit matrix.
// One warp per sample row. 8 int4 loads per lane (MLP=8, 512B/warp/iter),
// nibble build + 3-step shfl-OR to assemble each 32-entry word.
// ---------------------------------------------------------------------------
__global__ void __launch_bounds__(256) wisard_pack_kernel(const int* __restrict__ samples)
{
    int gtid   = blockIdx.x * blockDim.x + threadIdx.x;
    int b      = gtid >> 5;            // warp = sample row
    int lane   = gtid & 31;

    const int4* base = (const int4*)(samples + (size_t)b * ENTRY_SIZE) + lane;
    int4 v[8];
    #pragma unroll
    for (int it = 0; it < 8; ++it)
        v[it] = base[it * 32];         // entries it*128 + lane*4 .. +3

    unsigned j   = lane >> 3;          // word-within-iteration this lane's group builds
    unsigned sh  = 4u * (lane & 7);

    #pragma unroll
    for (int it = 0; it < 8; ++it) {
        unsigned nib = (unsigned)(v[it].x != 0)
                     | ((unsigned)(v[it].y != 0) << 1)
                     | ((unsigned)(v[it].z != 0) << 2)
                     | ((unsigned)(v[it].w != 0) << 3);
        unsigned x = nib << sh;
        x |= __shfl_xor_sync(0xffffffffu, x, 1);
        x |= __shfl_xor_sync(0xffffffffu, x, 2);
        x |= __shfl_xor_sync(0xffffffffu, x, 4);
        // lanes with (lane&7)==0 hold the completed word for group j
        if ((lane & 7) == 0)
            g_bitsT[(it * 4 + j) * BATCH + b] = x;
    }
}

// ---------------------------------------------------------------------------
// 32x32 bit-matrix transpose across a warp (block-swap butterfly).
// ---------------------------------------------------------------------------
__device__ __forceinline__ unsigned warp_bit_transpose(unsigned x, int lane)
{
    const unsigned masks[5] = { 0x0000FFFFu, 0x00FF00FFu, 0x0F0F0F0Fu,
                                0x33333333u, 0x55555555u };
    const int shifts[5] = { 16, 8, 4, 2, 1 };
    #pragma unroll
    for (int i = 0; i < 5; ++i) {
        int s = shifts[i];
        unsigned lm = masks[i];
        unsigned y = __shfl_xor_sync(0xffffffffu, x, s);
        if ((lane & s) == 0)
            x = (x & lm) | ((y & lm) << s);
        else
            x = (x & ~lm) | ((y & ~lm) >> s);
    }
    return x;
}

// Extract bit `lane` of word w (0/1)
#define BIT(w) (((w) >> lane) & 1u)

// ---------------------------------------------------------------------------
// Kernel 2: main WiSARD lookup, entry-major bit words.
// Grid: (BATCH/32, N_CLASSES). Block: 256 threads = 8 warps.
// Phase 2 is two-stage: build all 8 addresses (tree IMAD combine, dep depth
// ~5 instead of 16), then 8 back-to-back gathers.
// ---------------------------------------------------------------------------
__global__ void __launch_bounds__(256) wisard_main_kernel(
    const int*   __restrict__ tuple_mapping,  // [N_CLASSES][ENTRY_SIZE]
    const float* __restrict__ ram_table,      // [N_CLASSES][N_RAMS][N_ADDR]
    float*       __restrict__ out)            // [BATCH][N_CLASSES]
{
    const int c    = blockIdx.y;
    const int bw   = blockIdx.x;
    const int tid  = threadIdx.x;
    const int wid  = tid >> 5;
    const int lane = tid & 31;

    __shared__ __align__(16) int      tm_s[ENTRY_SIZE];     // 4 KB
    __shared__ unsigned               bitS_s[ENTRY_SIZE];   // 4 KB
    __shared__ float                  red[8][32];           // 1 KB

    #pragma unroll
    for (int i = 0; i < ENTRY_SIZE / 256; ++i)
        tm_s[tid + i * 256] = tuple_mapping[c * ENTRY_SIZE + tid + i * 256];

    // Phase 1: transpose this group's 32 bit-tiles into entry-major words.
    #pragma unroll
    for (int k = 0; k < 4; ++k) {
        int w = wid * 4 + k;
        unsigned x = g_bitsT[w * BATCH + bw * 32 + lane];
        x = warp_bit_transpose(x, lane);
        bitS_s[w * 32 + lane] = x;
    }

    __syncthreads();

    const float* tbl = ram_table + (size_t)c * (N_RAMS * N_ADDR);
    const int4* tmv = (const int4*)tm_s;

    // Phase 2a: build 8 addresses (one per RAM of this warp).
    unsigned addrs[8];
    #pragma unroll
    for (int i = 0; i < 8; ++i) {
        const int r = wid * 8 + i;
        int4 p0 = tmv[r * 4 + 0];
        int4 p1 = tmv[r * 4 + 1];
        int4 p2 = tmv[r * 4 + 2];
        int4 p3 = tmv[r * 4 + 3];

        // tuple element 0 is the MSB. Tree combine: pairs (IMAD), then
        // nibbles, bytes, final 16-bit address. Dep depth ~5.
        unsigned q0 = BIT(bitS_s[p0.x]) * 2u + BIT(bitS_s[p0.y]);  // bits 15..14
        unsigned q1 = BIT(bitS_s[p0.z]) * 2u + BIT(bitS_s[p0.w]);  // bits 13..12
        unsigned q2 = BIT(bitS_s[p1.x]) * 2u + BIT(bitS_s[p1.y]);
        unsigned q3 = BIT(bitS_s[p1.z]) * 2u + BIT(bitS_s[p1.w]);
        unsigned q4 = BIT(bitS_s[p2.x]) * 2u + BIT(bitS_s[p2.y]);
        unsigned q5 = BIT(bitS_s[p2.z]) * 2u + BIT(bitS_s[p2.w]);
        unsigned q6 = BIT(bitS_s[p3.x]) * 2u + BIT(bitS_s[p3.y]);
        unsigned q7 = BIT(bitS_s[p3.z]) * 2u + BIT(bitS_s[p3.w]);

        unsigned n0 = q0 * 4u + q1;       // bits 15..12
        unsigned n1 = q2 * 4u + q3;       // bits 11..8
        unsigned n2 = q4 * 4u + q5;       // bits 7..4
        unsigned n3 = q6 * 4u + q7;       // bits 3..0

        unsigned h0 = n0 * 16u + n1;      // bits 15..8
        unsigned h1 = n2 * 16u + n3;      // bits 7..0

        addrs[i] = h0 * 256u + h1;
    }

    // Phase 2b: 8 independent gathers, then accumulate.
    float acc0 = 0.f, acc1 = 0.f;
    #pragma unroll
    for (int i = 0; i < 8; ++i) {
        float v = __ldg(tbl + (((size_t)(wid * 8 + i)) << TUPLE_SIZE) + addrs[i]);
        if (i & 1) acc1 += v; else acc0 += v;
    }

    // Phase 3: reduce 8 warp partials per sample.
    red[wid][lane] = acc0 + acc1;
    __syncthreads();

    if (wid == 0) {
        float s = red[0][lane];
        #pragma unroll
        for (int w = 1; w < 8; ++w) s += red[w][lane];
        out[(bw * 32 + lane) * N_CLASSES + c] = s;
    }
}

// ---------------------------------------------------------------------------
// Launch
// ---------------------------------------------------------------------------
extern "C" void kernel_launch(void* const* d_in, const int* in_sizes, int n_in,
                              void* d_out, int out_size)
{
    const int*   samples       = (const int*)  d_in[0];  // [8192][1024] int32
    const int*   tuple_mapping = (const int*)  d_in[1];  // [10][1024]   int32
    const float* ram_table     = (const float*)d_in[2];  // [10][64][65536] float32
    float*       out           = (float*)d_out;          // [8192][10]   float32

    // Pack: 1 warp per sample -> 8192 warps -> 1024 blocks of 256
    wisard_pack_kernel<<<(BATCH * 32) / 256, 256>>>(samples);

    dim3 grid(BATCH / 32, N_CLASSES);   // 256 x 10 = 2560 blocks
    wisard_main_kernel<<<grid, 256>>>(tuple_mapping, ram_table, out);
}

// round 10
// speedup vs baseline: 3.2361x; 1.0355x over previous
#include <cuda_runtime.h>
#include <cuda_bf16.h>
#include <cstdint>

// Problem constants (Wisard_68401649156855)
#define ENTRY_SIZE 1024
#define N_CLASSES  10
#define TUPLE_SIZE 16
#define N_RAMS     64
#define N_ADDR     65536
#define BATCH      8192
#define WORDS_PER_ROW 32

// Scratch: transposed packed sample bits, bitsT[w][b]
// bit k of bitsT[w][b] = samples[b][w*32+k]
__device__ unsigned g_bitsT[WORDS_PER_ROW * BATCH];

// ---------------------------------------------------------------------------
// Kernel 1: pack samples (int32 0/1) -> bit matrix.
// One warp per sample row. 8 int4 loads per lane (MLP=8),
// nibble build + 3-step shfl-OR to assemble each 32-entry word.
// (unchanged from round 8 — known correct)
// ---------------------------------------------------------------------------
__global__ void __launch_bounds__(256) wisard_pack_kernel(const int* __restrict__ samples)
{
    int gtid   = blockIdx.x * blockDim.x + threadIdx.x;
    int b      = gtid >> 5;            // warp = sample row
    int lane   = gtid & 31;

    const int4* base = (const int4*)(samples + (size_t)b * ENTRY_SIZE) + lane;
    int4 v[8];
    #pragma unroll
    for (int it = 0; it < 8; ++it)
        v[it] = base[it * 32];

    unsigned j   = lane >> 3;
    unsigned sh  = 4u * (lane & 7);

    #pragma unroll
    for (int it = 0; it < 8; ++it) {
        unsigned nib = (unsigned)(v[it].x != 0)
                     | ((unsigned)(v[it].y != 0) << 1)
                     | ((unsigned)(v[it].z != 0) << 2)
                     | ((unsigned)(v[it].w != 0) << 3);
        unsigned x = nib << sh;
        x |= __shfl_xor_sync(0xffffffffu, x, 1);
        x |= __shfl_xor_sync(0xffffffffu, x, 2);
        x |= __shfl_xor_sync(0xffffffffu, x, 4);
        if ((lane & 7) == 0)
            g_bitsT[(it * 4 + j) * BATCH + b] = x;
    }
}

// ---------------------------------------------------------------------------
// 32x32 bit-matrix transpose across a warp (block-swap butterfly).
// out lane j, bit k  =  in lane k, bit j.
// ---------------------------------------------------------------------------
__device__ __forceinline__ unsigned warp_bit_transpose(unsigned x, int lane)
{
    const unsigned masks[5] = { 0x0000FFFFu, 0x00FF00FFu, 0x0F0F0F0Fu,
                                0x33333333u, 0x55555555u };
    const int shifts[5] = { 16, 8, 4, 2, 1 };
    #pragma unroll
    for (int i = 0; i < 5; ++i) {
        int s = shifts[i];
        unsigned lm = masks[i];
        unsigned y = __shfl_xor_sync(0xffffffffu, x, s);
        if ((lane & s) == 0)
            x = (x & lm) | ((y & lm) << s);
        else
            x = (x & ~lm) | ((y & ~lm) >> s);
    }
    return x;
}

// ---------------------------------------------------------------------------
// Kernel 2: main WiSARD lookup.
// Grid: (BATCH/32, N_CLASSES). Block: 256 threads = 8 warps, 32 samples/block.
// Phase 1: transpose bitsT tiles -> bitS_s[e] (entry-major sample words).
// Phase 2: warp wid handles RAMs [wid*8, wid*8+8), TWO RAMs per 32x32
//   bit transpose: lane l loads the entry-word for
//   tm[(r + (l>>4))*16 + 15-(l&15)]; after the butterfly, lane j holds
//   (addr_{r+1} << 16) | addr_r for SAMPLE j (MSB-first ordering verified).
//   Then 8 independent gathers per warp.
// Phase 3: cross-warp reduction.
// ---------------------------------------------------------------------------
__global__ void __launch_bounds__(256) wisard_main_kernel(
    const int*   __restrict__ tuple_mapping,  // [N_CLASSES][ENTRY_SIZE]
    const float* __restrict__ ram_table,      // [N_CLASSES][N_RAMS][N_ADDR]
    float*       __restrict__ out)            // [BATCH][N_CLASSES]
{
    const int c    = blockIdx.y;
    const int bw   = blockIdx.x;
    const int tid  = threadIdx.x;
    const int wid  = tid >> 5;
    const int lane = tid & 31;

    __shared__ __align__(16) int      tm_s[ENTRY_SIZE];     // 4 KB
    __shared__ unsigned               bitS_s[ENTRY_SIZE];   // 4 KB
    __shared__ float                  red[8][32];           // 1 KB

    #pragma unroll
    for (int i = 0; i < ENTRY_SIZE / 256; ++i)
        tm_s[tid + i * 256] = tuple_mapping[c * ENTRY_SIZE + tid + i * 256];

    // Phase 1: entry-major sample-bit words for this 32-sample group.
    #pragma unroll
    for (int k = 0; k < 4; ++k) {
        int w = wid * 4 + k;
        unsigned x = g_bitsT[w * BATCH + bw * 32 + lane];
        x = warp_bit_transpose(x, lane);
        bitS_s[w * 32 + lane] = x;          // bit j = sample j's entry (w*32+lane)
    }

    __syncthreads();

    const float* tbl = ram_table + (size_t)c * (N_RAMS * N_ADDR);

    // Per-lane tm index offset for the pair-transpose:
    //   lane l -> tuple slot (r + (l>>4))*16 + 15 - (l&15)
    const int tm_off = (lane >> 4) * 16 + 15 - (lane & 15);

    // Phase 2a: 4 transposes -> 8 addresses (packed two per word).
    unsigned aw[4];
    #pragma unroll
    for (int pair = 0; pair < 4; ++pair) {
        const int r = wid * 8 + pair * 2;
        unsigned w = bitS_s[tm_s[r * 16 + tm_off]];
        aw[pair] = warp_bit_transpose(w, lane);
    }

    // Phase 2b: 8 independent gathers (this lane = sample bw*32+lane).
    float acc0 = 0.f, acc1 = 0.f;
    #pragma unroll
    for (int pair = 0; pair < 4; ++pair) {
        const int r = wid * 8 + pair * 2;
        const float* base = tbl + ((size_t)r << TUPLE_SIZE);
        float v0 = __ldg(base + (aw[pair] & 0xFFFFu));
        float v1 = __ldg(base + N_ADDR + (aw[pair] >> 16));
        acc0 += v0;
        acc1 += v1;
    }

    // Phase 3: reduce the 8 warp partials per sample.
    red[wid][lane] = acc0 + acc1;
    __syncthreads();

    if (wid == 0) {
        float s = red[0][lane];
        #pragma unroll
        for (int w = 1; w < 8; ++w) s += red[w][lane];
        out[(bw * 32 + lane) * N_CLASSES + c] = s;
    }
}

// ---------------------------------------------------------------------------
// Launch
// ---------------------------------------------------------------------------
extern "C" void kernel_launch(void* const* d_in, const int* in_sizes, int n_in,
                              void* d_out, int out_size)
{
    const int*   samples       = (const int*)  d_in[0];  // [8192][1024] int32
    const int*   tuple_mapping = (const int*)  d_in[1];  // [10][1024]   int32
    const float* ram_table     = (const float*)d_in[2];  // [10][64][65536] float32
    float*       out           = (float*)d_out;          // [8192][10]   float32

    wisard_pack_kernel<<<(BATCH * 32) / 256, 256>>>(samples);

    dim3 grid(BATCH / 32, N_CLASSES);   // 256 x 10 = 2560 blocks
    wisard_main_kernel<<<grid, 256>>>(tuple_mapping, ram_table, out);
}